// round 13
// baseline (speedup 1.0000x reference)
#include <cuda_runtime.h>
#include <stdint.h>

#define BB 4
#define NP 8192
#define NG 8192
#define T  128
#define WPB (T / 32)                 // 4 warps per block
#define Q  8                         // queries per lane
#define QG 256                       // queries per warp-task
#define NQG (NP / QG)                // 32 query groups per batch
#define ASL 16                       // acc slices over gt pairs (worst case 4096/16=256 pairs)
#define CSL 16                       // com slices over pred pairs (4096/16=256 pairs)
#define TILEPAIRS 256                // max pairs per warp tile (8 KB)
#define NTA (BB * NQG * ASL)         // 2048 acc warp-tasks
#define NTC (BB * NQG * CSL)         // 2048 com warp-tasks
#define NTASK (NTA + NTC)            // 4096
#define NBLK 740                     // 5 CTAs/SM x 148 SMs, all co-resident
#define INF_BITS 0x7F800000u

// ---------------- device scratch (no allocs; counters self-reset per replay) ----------------
// pair-interleaved packed layout for point pair (2p, 2p+1):
//   entry[2p]   = { (x0,x1), (y0,y1) }
//   entry[2p+1] = { (z0,z1), (sq0,sq1) }
__device__ ulonglong2 g_pkgt[BB][NG];  // compacted valid gt (prefilled {0,0,0,inf})
__device__ ulonglong2 g_pkpr[BB][NP];  // all pred points
__device__ int      g_gtidx[BB][NG];   // original gt index of compacted entry
__device__ int      g_cnt[BB];
__device__ unsigned g_prmin[BB * NP];  // per-pred min d2 (float bits)
__device__ unsigned g_gtmin[BB * NG];  // per-ORIGINAL-gt min d2 (float bits)
__device__ int      g_bad;             // 1 => gt_valid is 1-byte bool; 0 => int32
__device__ int      g_bar1, g_bar2;    // grid barrier counters
__device__ int      g_task;            // dynamic warp-task counter
__device__ int      g_done;            // completion counter

// ---------------- packed f32x2 helpers ----------------
__device__ __forceinline__ unsigned long long f2pk(float lo, float hi) {
    unsigned long long r;
    asm("mov.b64 %0, {%1,%2};" : "=l"(r) : "f"(lo), "f"(hi));
    return r;
}
__device__ __forceinline__ unsigned long long fma2(unsigned long long a, unsigned long long b,
                                                   unsigned long long c) {
    unsigned long long r;
    asm("fma.rn.f32x2 %0, %1, %2, %3;" : "=l"(r) : "l"(a), "l"(b), "l"(c));
    return r;
}
__device__ __forceinline__ void upk(unsigned long long v, float& lo, float& hi) {
    asm("mov.b64 {%0,%1}, %2;" : "=f"(lo), "=f"(hi) : "l"(v));
}

// Grid barrier: all NBLK blocks co-resident (__launch_bounds__(128,5)).
__device__ __forceinline__ void grid_barrier(int* ctr) {
    __syncthreads();
    if (threadIdx.x == 0) {
        __threadfence();
        atomicAdd(ctr, 1);
        while (atomicAdd(ctr, 0) < NBLK) __nanosleep(64);
        __threadfence();
    }
    __syncthreads();
}

// One warp-autonomous Chamfer task: 256 queries vs one point-slice staged in
// the warp's PRIVATE smem tile. No block sync; smem broadcast via LDS.128.
template <bool IS_ACC>
__device__ __forceinline__ void do_task(int t, const float* __restrict__ pr,
                                        ulonglong2* __restrict__ tw, int lane) {
    int sl, qg, b;
    { int r;
      sl = t & (ASL - 1); r = t >> 4;   // ASL == CSL == 16
      qg = r & (NQG - 1); b = r >> 5; }
    int cnt = g_cnt[b];
    int qbase = qg * QG;

    int p0, p1;
    if (IS_ACC) {
        int npp = (cnt + 1) >> 1;              // pairs of compacted gt
        int Lp = (npp + ASL - 1) >> 4;         // pairs per slice (<= 256 worst case)
        p0 = sl * Lp;
        p1 = min(p0 + Lp, npp);
        if (p0 >= p1) return;
    } else {
        if (qbase >= cnt) return;              // whole task's queries invalid
        p0 = sl * TILEPAIRS;
        p1 = p0 + TILEPAIRS;
    }
    int npair = p1 - p0;

    // ---- fill warp-private tile: coalesced LDG.128 -> STS.128 ----
    const ulonglong2* __restrict__ pk = IS_ACC ? g_pkgt[b] : g_pkpr[b];
    __syncwarp();
    for (int i = lane; i < 2 * npair; i += 32) tw[i] = pk[2 * p0 + i];
    __syncwarp();

    // ---- query setup ----
    unsigned long long q2x[Q], q2y[Q], q2z[Q];
    float qsq[Q], m0[Q], m1[Q];
#pragma unroll
    for (int q = 0; q < Q; q++) {
        int qq = qbase + q * 32 + lane;
        float x, y, z, sq;
        if (IS_ACC) {
            const float* p = pr + ((size_t)b * NP + qq) * 3;
            x = p[0]; y = p[1]; z = p[2];
            sq = x * x + y * y + z * z;
        } else {
            const float* f = reinterpret_cast<const float*>(&g_pkgt[b][0]);
            int e = (qq >> 1) * 8 + (qq & 1);
            x = f[e]; y = f[e + 2]; z = f[e + 4]; sq = f[e + 6];
        }
        float nx = -2.f * x, ny = -2.f * y, nz = -2.f * z;
        q2x[q] = f2pk(nx, nx); q2y[q] = f2pk(ny, ny); q2z[q] = f2pk(nz, nz);
        qsq[q] = sq;
        m0[q] = __uint_as_float(INF_BITS);
        m1[q] = __uint_as_float(INF_BITS);
    }

    // ---- hot loop: lane-uniform LDS.128 broadcast ----
#pragma unroll 2
    for (int k = 0; k < npair; k++) {
        ulonglong2 v1 = tw[2 * k];        // (x0,x1),(y0,y1)
        ulonglong2 v2 = tw[2 * k + 1];    // (z0,z1),(sq0,sq1)
#pragma unroll
        for (int q = 0; q < Q; q++) {
            unsigned long long t2 = fma2(q2x[q], v1.x, fma2(q2y[q], v1.y, fma2(q2z[q], v2.x, v2.y)));
            float tl, th; upk(t2, tl, th);
            m0[q] = fminf(m0[q], tl);
            m1[q] = fminf(m1[q], th);
        }
    }

    // ---- epilogue ----
#pragma unroll
    for (int q = 0; q < Q; q++) {
        int qq = qbase + q * 32 + lane;
        float m = fmaxf(fminf(m0[q], m1[q]) + qsq[q], 0.f);
        if (IS_ACC) {
            atomicMin(&g_prmin[b * NP + qq], __float_as_uint(m));
        } else if (qq < cnt) {
            int orig = g_gtidx[b][qq];
            atomicMin(&g_gtmin[b * NG + orig], __float_as_uint(m));
        }
    }
}

// ---------------- the single persistent kernel ----------------
__global__ void __launch_bounds__(T, 5) k_all(const float* __restrict__ pr,
                                              const float* __restrict__ gt,
                                              const void* __restrict__ valid,
                                              float* __restrict__ out) {
    __shared__ __align__(16) ulonglong2 tiles[WPB][2 * TILEPAIRS];  // 8 KB per warp, 32 KB total
    int tid = threadIdx.x;
    int gtid = blockIdx.x * T + tid;
    int gstride = NBLK * T;   // 94720 threads

    // ======== Phase A: resets + build packed pred + prefill packed gt + detect ========
    for (int k = gtid; k < BB * NP; k += gstride) g_prmin[k] = INF_BITS;
    for (int k = gtid; k < BB * NG; k += gstride) g_gtmin[k] = INF_BITS;

    for (int i2 = gtid; i2 < BB * (NP / 2); i2 += gstride) {
        int b = i2 >> 12;                 // / (NP/2)
        int p2 = i2 & (NP / 2 - 1);
        const float* p = pr + ((size_t)b * NP + p2 * 2) * 3;
        float x0 = p[0], y0 = p[1], z0 = p[2];
        float x1 = p[3], y1 = p[4], z1 = p[5];
        float s0 = x0 * x0 + y0 * y0 + z0 * z0;
        float s1 = x1 * x1 + y1 * y1 + z1 * z1;
        ulonglong2 e0, e1;
        e0.x = f2pk(x0, x1); e0.y = f2pk(y0, y1);
        e1.x = f2pk(z0, z1); e1.y = f2pk(s0, s1);
        g_pkpr[b][2 * p2] = e0;
        g_pkpr[b][2 * p2 + 1] = e1;
    }
    {
        float finf = __uint_as_float(INF_BITS);
        unsigned long long ZZ = f2pk(0.f, 0.f), II = f2pk(finf, finf);
        ulonglong2 eZ, eI;
        eZ.x = ZZ; eZ.y = ZZ;
        eI.x = ZZ; eI.y = II;
        for (int i2 = gtid; i2 < BB * (NG / 2); i2 += gstride) {
            int b = i2 >> 12;
            int p2 = i2 & (NG / 2 - 1);
            g_pkgt[b][2 * p2] = eZ;
            g_pkgt[b][2 * p2 + 1] = eI;
        }
    }
    {
        const unsigned* w = (const unsigned*)valid;  // read (BB*NG)/4 words: safe either layout
        int found = 0;
        for (int k = gtid; k < (BB * NG) / 4; k += gstride)
            if (w[k] > 1u) found = 1;
        if (found) g_bad = 1;
    }
    grid_barrier(&g_bar1);

    // ======== Phase B: warp-aggregated compaction into packed gt ========
    if (gtid < BB * NG) {
        int fmt_byte = g_bad;
        int b = gtid >> 13;
        int g = gtid & (NG - 1);
        bool v;
        if (fmt_byte)
            v = (reinterpret_cast<const unsigned char*>(valid)[gtid] != 0);
        else
            v = (reinterpret_cast<const int*>(valid)[gtid] != 0);

        unsigned mask = __ballot_sync(0xffffffffu, v);
        int lane = tid & 31;
        int base = 0;
        if (lane == 0 && mask) base = atomicAdd(&g_cnt[b], __popc(mask));
        base = __shfl_sync(0xffffffffu, base, 0);
        if (v) {
            int p = base + __popc(mask & ((1u << lane) - 1u));
            const float* sgt = gt + (size_t)gtid * 3;
            float x = sgt[0], y = sgt[1], z = sgt[2];
            float sq = x * x + y * y + z * z;
            float* f = reinterpret_cast<float*>(&g_pkgt[b][0]);
            int e = (p >> 1) * 8 + (p & 1);
            f[e] = x; f[e + 2] = y; f[e + 4] = z; f[e + 6] = sq;
            g_gtidx[b][p] = g;
        }
    }
    grid_barrier(&g_bar2);

    // ======== Phase C: warp-autonomous dynamic task loop (NO block sync) ========
    {
        int lane = tid & 31;
        ulonglong2* tw = &tiles[tid >> 5][0];
        while (true) {
            int t = 0;
            if (lane == 0) t = atomicAdd(&g_task, 1);
            t = __shfl_sync(0xffffffffu, t, 0);
            if (t >= NTASK) break;
            if (t < NTA) do_task<true>(t, pr, tw, lane);
            else         do_task<false>(t - NTA, pr, tw, lane);
        }
    }

    // ======== Phase D: last block reduces + resets counters ========
    __shared__ bool isLast;
    __shared__ float sa;
    __shared__ float sc[BB];
    __threadfence();
    __syncthreads();
    if (tid == 0) {
        int prev = atomicAdd(&g_done, 1);
        isLast = (prev == NBLK - 1);
        if (isLast) __threadfence();
        sa = 0.f;
    }
    if (tid < BB) sc[tid] = 0.f;
    __syncthreads();
    if (!isLast) return;

    float la = 0.f;
    for (int i = tid; i < BB * NP; i += T)
        la += __uint_as_float(g_prmin[i]);
    atomicAdd(&sa, la);

    for (int bb = 0; bb < BB; bb++) {
        float lc = 0.f;
        for (int i = tid; i < NG; i += T) {
            unsigned v = g_gtmin[bb * NG + i];
            if (v != INF_BITS) lc += __uint_as_float(v);
        }
        atomicAdd(&sc[bb], lc);
    }
    __syncthreads();

    if (tid == 0) {
        float loss_acc = sa / (float)(BB * NP);
        float loss_com = 0.f;
        for (int bb = 0; bb < BB; bb++)
            loss_com += sc[bb] / fmaxf((float)g_cnt[bb], 1.f);
        loss_com /= (float)BB;
        out[0] = 2.f * (loss_acc + loss_com);  // acc + com + cd, cd = acc + com

        for (int bb = 0; bb < BB; bb++) g_cnt[bb] = 0;
        g_bad = 0; g_bar1 = 0; g_bar2 = 0; g_task = 0; g_done = 0;
    }
}

// ---------------- launch ----------------
extern "C" void kernel_launch(void* const* d_in, const int* in_sizes, int n_in,
                              void* d_out, int out_size) {
    const float* pr    = (const float*)d_in[0];  // [B,NP,3] f32
    const float* gt    = (const float*)d_in[1];  // [B,NG,3] f32
    const void*  valid = d_in[2];                // [B,NG] bool(1B) or int32

    k_all<<<NBLK, T>>>(pr, gt, valid, (float*)d_out);
}

// round 14
// speedup vs baseline: 1.0142x; 1.0142x over previous
#include <cuda_runtime.h>
#include <stdint.h>

#define BB 4
#define NP 8192
#define NG 8192
#define T  128          // threads per block
#define Q  8            // queries per thread
#define SLA 32          // gt slices (acc direction)  -> ~128-pt tiles
#define PS 64           // pred slices (com direction) -> 128-pt tiles
#define PSL (NP / PS)   // 128 pred points per slice
#define GRID_X (NP / (T * Q))           // 8
#define NTA (GRID_X * SLA * BB)         // 1024 acc tasks
#define NTC (GRID_X * PS * BB)          // 2048 com tasks
#define NBLK 740                        // 5 CTAs/SM x 148 SMs, all co-resident
#define TILE_MAX 256                    // max points per tile (4 KB smem)

#define INF_BITS 0x7F800000u

// ---------------- device scratch (no allocs; all counters self-reset per replay) ----------------
__device__ float    g_gt[BB][3][NG];   // compacted valid gt, SoA ([cnt,NG) = stale, never used)
__device__ float    g_gtsq[BB][NG];    // |g|^2 per compacted gt
__device__ int      g_gtidx[BB][NG];   // original gt index of compacted entry
__device__ int      g_cnt[BB];         // zero-init (.bss), reset at end of each replay
__device__ unsigned g_prmin[BB * NP];  // per-pred min d2 (float bits)
__device__ unsigned g_gtmin[BB * NG];  // per-ORIGINAL-gt min d2 (float bits)
__device__ int      g_bad;             // 1 => gt_valid is 1-byte bool; 0 => int32
__device__ int      g_bar1, g_bar2;    // grid barrier counters
__device__ int      g_taskA, g_taskC;  // dynamic task counters (acc / com)
__device__ int      g_done;            // completion counter

// ---------------- packed f32x2 helpers ----------------
__device__ __forceinline__ unsigned long long f2pk(float lo, float hi) {
    unsigned long long r;
    asm("mov.b64 %0, {%1,%2};" : "=l"(r) : "f"(lo), "f"(hi));
    return r;
}
__device__ __forceinline__ unsigned long long fma2(unsigned long long a, unsigned long long b,
                                                   unsigned long long c) {
    unsigned long long r;
    asm("fma.rn.f32x2 %0, %1, %2, %3;" : "=l"(r) : "l"(a), "l"(b), "l"(c));
    return r;
}
__device__ __forceinline__ void upk(unsigned long long v, float& lo, float& hi) {
    asm("mov.b64 {%0,%1}, %2;" : "=f"(lo), "=f"(hi) : "l"(v));
}

// Grid barrier: safe because all NBLK blocks are co-resident
// (__launch_bounds__(128,5): regs<=102 (need ~94), smem 5x4.2KB = 21KB).
__device__ __forceinline__ void grid_barrier(int* ctr) {
    __syncthreads();
    if (threadIdx.x == 0) {
        __threadfence();                 // release this block's prior writes
        atomicAdd(ctr, 1);
        while (atomicAdd(ctr, 0) < NBLK) __nanosleep(64);
        __threadfence();                 // acquire other blocks' writes
    }
    __syncthreads();
}

// One Chamfer tile-task, specialized per direction (no runtime is_acc in hot loop).
template <bool IS_ACC>
__device__ __forceinline__ void do_task(int task, const float* __restrict__ pr,
                                        float4* s, int tid) {
    int xg = task & (GRID_X - 1);
    int zz = task >> 3;                 // GRID_X = 8
    int b, slice;
    if (IS_ACC) { b = zz >> 5; slice = zz & (SLA - 1); }
    else        { b = zz >> 6; slice = zz & (PS - 1); }
    int cnt = g_cnt[b];

    int qbase = xg * (T * Q);
    int tileLen, t0;
    if (IS_ACC) {
        int npad = (cnt + 7) & ~7;
        int L = (((npad + SLA - 1) / SLA) + 7) & ~7;   // slice len, mult of 8, <= 256
        t0 = slice * L;
        int t1 = min(t0 + L, npad);
        if (t0 >= t1) return;
        tileLen = t1 - t0;
    } else {
        t0 = slice * PSL;
        tileLen = PSL;
        if (qbase >= cnt) return;
    }

    if (IS_ACC) {
        for (int i = tid; i < tileLen; i += T) {
            int idx = t0 + i;
            float x, y, z, sq;
            if (idx < cnt) {
                x = g_gt[b][0][idx]; y = g_gt[b][1][idx]; z = g_gt[b][2][idx];
                sq = g_gtsq[b][idx];
            } else {  // in-register sentinel (pad region, <= 7 entries)
                x = 0.f; y = 0.f; z = 0.f; sq = __uint_as_float(INF_BITS);
            }
            float* base = reinterpret_cast<float*>(&s[(i >> 1) * 2]);
            int h = i & 1;
            base[0 + h] = x; base[2 + h] = y; base[4 + h] = z; base[6 + h] = sq;
        }
    } else {
        for (int i = tid; i < tileLen; i += T) {
            const float* p = pr + ((size_t)b * NP + t0 + i) * 3;
            float x = p[0], y = p[1], z = p[2];
            float sq = x * x + y * y + z * z;
            float* base = reinterpret_cast<float*>(&s[(i >> 1) * 2]);
            int h = i & 1;
            base[0 + h] = x; base[2 + h] = y; base[4 + h] = z; base[6 + h] = sq;
        }
    }
    __syncthreads();

    unsigned long long q2x[Q], q2y[Q], q2z[Q];
    float qsq[Q], m0[Q], m1[Q];
#pragma unroll
    for (int q = 0; q < Q; q++) {
        int qq = qbase + tid + q * T;
        float x, y, z, sq;
        if (IS_ACC) {
            const float* p = pr + ((size_t)b * NP + qq) * 3;
            x = p[0]; y = p[1]; z = p[2];
            sq = x * x + y * y + z * z;
        } else {
            // qq >= cnt reads stale data; result discarded at the atomic
            x = g_gt[b][0][qq]; y = g_gt[b][1][qq]; z = g_gt[b][2][qq];
            sq = (qq < cnt) ? g_gtsq[b][qq] : 0.f;
        }
        float nx = -2.f * x, ny = -2.f * y, nz = -2.f * z;
        q2x[q] = f2pk(nx, nx); q2y[q] = f2pk(ny, ny); q2z[q] = f2pk(nz, nz);
        qsq[q] = sq;
        m0[q] = __uint_as_float(INF_BITS);
        m1[q] = __uint_as_float(INF_BITS);
    }

    int pairs = tileLen >> 1;
#pragma unroll 2
    for (int k = 0; k < pairs; k++) {
        float4 a  = s[k * 2];
        float4 bv = s[k * 2 + 1];
        unsigned long long gx = f2pk(a.x, a.y);
        unsigned long long gy = f2pk(a.z, a.w);
        unsigned long long gz = f2pk(bv.x, bv.y);
        unsigned long long gs = f2pk(bv.z, bv.w);
#pragma unroll
        for (int q = 0; q < Q; q++) {
            unsigned long long t = fma2(q2x[q], gx, fma2(q2y[q], gy, fma2(q2z[q], gz, gs)));
            float tl, th; upk(t, tl, th);
            m0[q] = fminf(m0[q], tl);
            m1[q] = fminf(m1[q], th);
        }
    }

#pragma unroll
    for (int q = 0; q < Q; q++) {
        int qq = qbase + tid + q * T;
        float m = fmaxf(fminf(m0[q], m1[q]) + qsq[q], 0.f);
        if (IS_ACC) {
            atomicMin(&g_prmin[b * NP + qq], __float_as_uint(m));
        } else if (qq < cnt) {
            int orig = g_gtidx[b][qq];
            atomicMin(&g_gtmin[b * NG + orig], __float_as_uint(m));
        }
    }
}

// ---------------- the single persistent kernel ----------------
__global__ void __launch_bounds__(T, 5) k_all(const float* __restrict__ pr,
                                              const float* __restrict__ gt,
                                              const void* __restrict__ valid,
                                              float* __restrict__ out) {
    int tid = threadIdx.x;
    int gtid = blockIdx.x * T + tid;
    int gstride = NBLK * T;   // 94720 threads

    // ======== Phase A: reset min arrays + detect gt_valid format ========
    for (int k = gtid; k < BB * NP; k += gstride) g_prmin[k] = INF_BITS;
    for (int k = gtid; k < BB * NG; k += gstride) g_gtmin[k] = INF_BITS;
    {
        // read only (BB*NG)/4 = 8192 words: safe under both layouts.
        // byte-bool packs 4 flags/word -> some word > 1; int32 words are all 0/1.
        const unsigned* w = (const unsigned*)valid;
        int found = 0;
        for (int k = gtid; k < (BB * NG) / 4; k += gstride)
            if (w[k] > 1u) found = 1;
        if (found) g_bad = 1;
    }
    grid_barrier(&g_bar1);

    // ======== Phase B: warp-aggregated compaction (first BB*NG threads) ========
    if (gtid < BB * NG) {
        int fmt_byte = g_bad;   // 1 => byte-bool
        int b = gtid >> 13;     // / NG
        int g = gtid & (NG - 1);
        bool v;
        if (fmt_byte)
            v = (reinterpret_cast<const unsigned char*>(valid)[gtid] != 0);
        else
            v = (reinterpret_cast<const int*>(valid)[gtid] != 0);

        unsigned mask = __ballot_sync(0xffffffffu, v);
        int lane = tid & 31;
        int base = 0;
        if (lane == 0 && mask) base = atomicAdd(&g_cnt[b], __popc(mask));
        base = __shfl_sync(0xffffffffu, base, 0);
        if (v) {
            int p = base + __popc(mask & ((1u << lane) - 1u));
            const float* sgt = gt + (size_t)gtid * 3;
            float x = sgt[0], y = sgt[1], z = sgt[2];
            g_gt[b][0][p] = x;
            g_gt[b][1][p] = y;
            g_gt[b][2][p] = z;
            g_gtsq[b][p]  = x * x + y * y + z * z;
            g_gtidx[b][p] = g;
        }
    }
    grid_barrier(&g_bar2);

    // ======== Phase C: dynamic task loops (acc first, then com) ========
    __shared__ __align__(16) float4 s[TILE_MAX];  // 4 KB
    __shared__ int s_task;

    while (true) {
        if (tid == 0) s_task = atomicAdd(&g_taskA, 1);
        __syncthreads();
        int task = s_task;
        if (task >= NTA) break;
        do_task<true>(task, pr, s, tid);
        __syncthreads();   // protect smem tile + s_task reuse
    }
    while (true) {
        if (tid == 0) s_task = atomicAdd(&g_taskC, 1);
        __syncthreads();
        int task = s_task;
        if (task >= NTC) break;
        do_task<false>(task, pr, s, tid);
        __syncthreads();
    }

    // ======== Phase D: last block reduces + resets all counters ========
    __shared__ bool isLast;
    __shared__ float sa;
    __shared__ float sc[BB];
    __threadfence();
    __syncthreads();
    if (tid == 0) {
        int prev = atomicAdd(&g_done, 1);
        isLast = (prev == NBLK - 1);
        if (isLast) __threadfence();   // acquire all blocks' writes
        sa = 0.f;
    }
    if (tid < BB) sc[tid] = 0.f;
    __syncthreads();
    if (!isLast) return;

    float la = 0.f;
    for (int i = tid; i < BB * NP; i += T)
        la += __uint_as_float(g_prmin[i]);
    atomicAdd(&sa, la);

    for (int bb = 0; bb < BB; bb++) {
        float lc = 0.f;
        for (int i = tid; i < NG; i += T) {
            unsigned v = g_gtmin[bb * NG + i];
            if (v != INF_BITS) lc += __uint_as_float(v);  // only valid gt were written
        }
        atomicAdd(&sc[bb], lc);
    }
    __syncthreads();

    if (tid == 0) {
        float loss_acc = sa / (float)(BB * NP);
        float loss_com = 0.f;
        for (int bb = 0; bb < BB; bb++)
            loss_com += sc[bb] / fmaxf((float)g_cnt[bb], 1.f);
        loss_com /= (float)BB;
        out[0] = 2.f * (loss_acc + loss_com);  // acc + com + cd, cd = acc + com

        // reset ALL mutable state for the next graph replay
        for (int bb = 0; bb < BB; bb++) g_cnt[bb] = 0;
        g_bad = 0; g_bar1 = 0; g_bar2 = 0; g_taskA = 0; g_taskC = 0; g_done = 0;
    }
}

// ---------------- launch ----------------
extern "C" void kernel_launch(void* const* d_in, const int* in_sizes, int n_in,
                              void* d_out, int out_size) {
    const float* pr    = (const float*)d_in[0];  // [B,NP,3] f32
    const float* gt    = (const float*)d_in[1];  // [B,NG,3] f32
    const void*  valid = d_in[2];                // [B,NG] bool(1B) or int32

    k_all<<<NBLK, T>>>(pr, gt, valid, (float*)d_out);
}

// round 15
// speedup vs baseline: 1.1141x; 1.0985x over previous
#include <cuda_runtime.h>
#include <stdint.h>

#define BB 4
#define NP 8192
#define NG 8192
#define T  128          // threads per block
#define Q  8            // queries per thread
#define SLA 32          // gt slices (acc direction)  -> ~128-pt tiles
#define PS 64           // pred slices (com direction) -> 128-pt tiles
#define PSL (NP / PS)   // 128 pred points per slice
#define GRID_X (NP / (T * Q))           // 8
#define NTA (GRID_X * SLA * BB)         // 1024 acc tasks
#define NTC (GRID_X * PS * BB)          // 2048 com tasks
#define NBLK 740                        // 5 CTAs/SM x 148 SMs, all co-resident
#define TILE_MAX 256                    // max points per tile (4 KB smem)

#define INF_BITS 0x7F800000u

// ---------------- device scratch (no allocs; all state self-resets per replay) ----------------
__device__ float    g_gt[BB][3][NG];   // compacted valid gt, SoA ([cnt,NG) = stale, never used)
__device__ float    g_gtsq[BB][NG];    // |g|^2 per compacted gt
__device__ int      g_gtidx[BB][NG];   // original gt index of compacted entry
__device__ int      g_cnt[BB];         // zero-init (.bss), reset at end of each replay
__device__ unsigned g_prmin[BB * NP];  // per-pred min d2 (float bits)
__device__ unsigned g_gtmin[BB * NG];  // per-ORIGINAL-gt min d2 (float bits)
__device__ int      g_bad;             // 1 => gt_valid is 1-byte bool; 0 => int32
__device__ int      g_bar1, g_bar2;    // grid barrier arrival counters
__device__ int      g_rel1, g_rel2;    // grid barrier release flags (polled via plain loads)
__device__ int      g_done;            // completion counter

// ---------------- packed f32x2 helpers ----------------
__device__ __forceinline__ unsigned long long f2pk(float lo, float hi) {
    unsigned long long r;
    asm("mov.b64 %0, {%1,%2};" : "=l"(r) : "f"(lo), "f"(hi));
    return r;
}
__device__ __forceinline__ unsigned long long fma2(unsigned long long a, unsigned long long b,
                                                   unsigned long long c) {
    unsigned long long r;
    asm("fma.rn.f32x2 %0, %1, %2, %3;" : "=l"(r) : "l"(a), "l"(b), "l"(c));
    return r;
}
__device__ __forceinline__ void upk(unsigned long long v, float& lo, float& hi) {
    asm("mov.b64 {%0,%1}, %2;" : "=f"(lo), "=f"(hi) : "l"(v));
}

// Flag-release grid barrier: ONE atomicAdd per block for arrival; waiters poll a
// plain volatile word (L2 read path — no atomic-ALU serialization). Safe because
// all NBLK blocks are co-resident (__launch_bounds__(128,5): regs<=102, smem ~4KB).
__device__ __forceinline__ void grid_barrier(int* ctr, int* rel) {
    __syncthreads();
    if (threadIdx.x == 0) {
        __threadfence();                       // release this block's prior writes
        int prev = atomicAdd(ctr, 1);
        if (prev == NBLK - 1) {
            __threadfence();
            *(volatile int*)rel = 1;           // release everyone
        } else {
            while (*(volatile int*)rel == 0) __nanosleep(128);
        }
        __threadfence();                       // acquire other blocks' writes
    }
    __syncthreads();
}

// One Chamfer tile-task, specialized per direction (no runtime is_acc in hot loop).
template <bool IS_ACC>
__device__ __forceinline__ void do_task(int task, const float* __restrict__ pr,
                                        float4* s, int tid) {
    int xg = task & (GRID_X - 1);
    int zz = task >> 3;                 // GRID_X = 8
    int b, slice;
    if (IS_ACC) { b = zz >> 5; slice = zz & (SLA - 1); }
    else        { b = zz >> 6; slice = zz & (PS - 1); }
    int cnt = g_cnt[b];

    int qbase = xg * (T * Q);
    int tileLen, t0;
    if (IS_ACC) {
        int npad = (cnt + 7) & ~7;
        int L = (((npad + SLA - 1) / SLA) + 7) & ~7;   // slice len, mult of 8, <= 256
        t0 = slice * L;
        int t1 = min(t0 + L, npad);
        if (t0 >= t1) return;
        tileLen = t1 - t0;
    } else {
        t0 = slice * PSL;
        tileLen = PSL;
        if (qbase >= cnt) return;
    }

    if (IS_ACC) {
        for (int i = tid; i < tileLen; i += T) {
            int idx = t0 + i;
            float x, y, z, sq;
            if (idx < cnt) {
                x = g_gt[b][0][idx]; y = g_gt[b][1][idx]; z = g_gt[b][2][idx];
                sq = g_gtsq[b][idx];
            } else {  // in-register sentinel (pad region, <= 7 entries)
                x = 0.f; y = 0.f; z = 0.f; sq = __uint_as_float(INF_BITS);
            }
            float* base = reinterpret_cast<float*>(&s[(i >> 1) * 2]);
            int h = i & 1;
            base[0 + h] = x; base[2 + h] = y; base[4 + h] = z; base[6 + h] = sq;
        }
    } else {
        for (int i = tid; i < tileLen; i += T) {
            const float* p = pr + ((size_t)b * NP + t0 + i) * 3;
            float x = p[0], y = p[1], z = p[2];
            float sq = x * x + y * y + z * z;
            float* base = reinterpret_cast<float*>(&s[(i >> 1) * 2]);
            int h = i & 1;
            base[0 + h] = x; base[2 + h] = y; base[4 + h] = z; base[6 + h] = sq;
        }
    }
    __syncthreads();

    unsigned long long q2x[Q], q2y[Q], q2z[Q];
    float qsq[Q], m0[Q], m1[Q];
#pragma unroll
    for (int q = 0; q < Q; q++) {
        int qq = qbase + tid + q * T;
        float x, y, z, sq;
        if (IS_ACC) {
            const float* p = pr + ((size_t)b * NP + qq) * 3;
            x = p[0]; y = p[1]; z = p[2];
            sq = x * x + y * y + z * z;
        } else {
            // qq >= cnt reads stale data; result discarded at the atomic
            x = g_gt[b][0][qq]; y = g_gt[b][1][qq]; z = g_gt[b][2][qq];
            sq = (qq < cnt) ? g_gtsq[b][qq] : 0.f;
        }
        float nx = -2.f * x, ny = -2.f * y, nz = -2.f * z;
        q2x[q] = f2pk(nx, nx); q2y[q] = f2pk(ny, ny); q2z[q] = f2pk(nz, nz);
        qsq[q] = sq;
        m0[q] = __uint_as_float(INF_BITS);
        m1[q] = __uint_as_float(INF_BITS);
    }

    int pairs = tileLen >> 1;
#pragma unroll 2
    for (int k = 0; k < pairs; k++) {
        float4 a  = s[k * 2];
        float4 bv = s[k * 2 + 1];
        unsigned long long gx = f2pk(a.x, a.y);
        unsigned long long gy = f2pk(a.z, a.w);
        unsigned long long gz = f2pk(bv.x, bv.y);
        unsigned long long gs = f2pk(bv.z, bv.w);
#pragma unroll
        for (int q = 0; q < Q; q++) {
            unsigned long long t = fma2(q2x[q], gx, fma2(q2y[q], gy, fma2(q2z[q], gz, gs)));
            float tl, th; upk(t, tl, th);
            m0[q] = fminf(m0[q], tl);
            m1[q] = fminf(m1[q], th);
        }
    }

#pragma unroll
    for (int q = 0; q < Q; q++) {
        int qq = qbase + tid + q * T;
        float m = fmaxf(fminf(m0[q], m1[q]) + qsq[q], 0.f);
        if (IS_ACC) {
            atomicMin(&g_prmin[b * NP + qq], __float_as_uint(m));
        } else if (qq < cnt) {
            int orig = g_gtidx[b][qq];
            atomicMin(&g_gtmin[b * NG + orig], __float_as_uint(m));
        }
    }
}

// ---------------- the single persistent kernel ----------------
__global__ void __launch_bounds__(T, 5) k_all(const float* __restrict__ pr,
                                              const float* __restrict__ gt,
                                              const void* __restrict__ valid,
                                              float* __restrict__ out) {
    int tid = threadIdx.x;
    int gtid = blockIdx.x * T + tid;
    int gstride = NBLK * T;   // 94720 threads

    // ======== Phase A: reset min arrays + detect gt_valid format ========
    for (int k = gtid; k < BB * NP; k += gstride) g_prmin[k] = INF_BITS;
    for (int k = gtid; k < BB * NG; k += gstride) g_gtmin[k] = INF_BITS;
    {
        // read only (BB*NG)/4 = 8192 words: safe under both layouts.
        // byte-bool packs 4 flags/word -> some word > 1; int32 words are all 0/1.
        const unsigned* w = (const unsigned*)valid;
        int found = 0;
        for (int k = gtid; k < (BB * NG) / 4; k += gstride)
            if (w[k] > 1u) found = 1;
        if (found) g_bad = 1;
    }
    grid_barrier(&g_bar1, &g_rel1);

    // ======== Phase B: warp-aggregated compaction (first BB*NG threads) ========
    if (gtid < BB * NG) {
        int fmt_byte = g_bad;   // 1 => byte-bool
        int b = gtid >> 13;     // / NG
        int g = gtid & (NG - 1);
        bool v;
        if (fmt_byte)
            v = (reinterpret_cast<const unsigned char*>(valid)[gtid] != 0);
        else
            v = (reinterpret_cast<const int*>(valid)[gtid] != 0);

        unsigned mask = __ballot_sync(0xffffffffu, v);
        int lane = tid & 31;
        int base = 0;
        if (lane == 0 && mask) base = atomicAdd(&g_cnt[b], __popc(mask));
        base = __shfl_sync(0xffffffffu, base, 0);
        if (v) {
            int p = base + __popc(mask & ((1u << lane) - 1u));
            const float* sgt = gt + (size_t)gtid * 3;
            float x = sgt[0], y = sgt[1], z = sgt[2];
            g_gt[b][0][p] = x;
            g_gt[b][1][p] = y;
            g_gt[b][2][p] = z;
            g_gtsq[b][p]  = x * x + y * y + z * z;
            g_gtidx[b][p] = g;
        }
    }
    grid_barrier(&g_bar2, &g_rel2);

    // ======== Phase C: STATIC snake task loop (no queue atomics) ========
    __shared__ __align__(16) float4 s[TILE_MAX];  // 4 KB

    for (int t = blockIdx.x; t < NTA + NTC; t += NBLK) {
        if (t < NTA) do_task<true>(t, pr, s, tid);
        else         do_task<false>(t - NTA, pr, s, tid);
        __syncthreads();   // protect smem tile reuse across iterations
    }

    // ======== Phase D: last block reduces + resets all state ========
    __shared__ bool isLast;
    __shared__ float sa;
    __shared__ float sc[BB];
    __threadfence();
    __syncthreads();
    if (tid == 0) {
        int prev = atomicAdd(&g_done, 1);
        isLast = (prev == NBLK - 1);
        if (isLast) __threadfence();   // acquire all blocks' writes
        sa = 0.f;
    }
    if (tid < BB) sc[tid] = 0.f;
    __syncthreads();
    if (!isLast) return;

    float la = 0.f;
    for (int i = tid; i < BB * NP; i += T)
        la += __uint_as_float(g_prmin[i]);
    atomicAdd(&sa, la);

    for (int bb = 0; bb < BB; bb++) {
        float lc = 0.f;
        for (int i = tid; i < NG; i += T) {
            unsigned v = g_gtmin[bb * NG + i];
            if (v != INF_BITS) lc += __uint_as_float(v);  // only valid gt were written
        }
        atomicAdd(&sc[bb], lc);
    }
    __syncthreads();

    if (tid == 0) {
        float loss_acc = sa / (float)(BB * NP);
        float loss_com = 0.f;
        for (int bb = 0; bb < BB; bb++)
            loss_com += sc[bb] / fmaxf((float)g_cnt[bb], 1.f);
        loss_com /= (float)BB;
        out[0] = 2.f * (loss_acc + loss_com);  // acc + com + cd, cd = acc + com

        // reset ALL mutable state for the next graph replay
        for (int bb = 0; bb < BB; bb++) g_cnt[bb] = 0;
        g_bad = 0;
        g_bar1 = 0; g_bar2 = 0;
        g_rel1 = 0; g_rel2 = 0;
        g_done = 0;
    }
}

// ---------------- launch ----------------
extern "C" void kernel_launch(void* const* d_in, const int* in_sizes, int n_in,
                              void* d_out, int out_size) {
    const float* pr    = (const float*)d_in[0];  // [B,NP,3] f32
    const float* gt    = (const float*)d_in[1];  // [B,NG,3] f32
    const void*  valid = d_in[2];                // [B,NG] bool(1B) or int32

    k_all<<<NBLK, T>>>(pr, gt, valid, (float*)d_out);
}

// round 17
// speedup vs baseline: 1.1731x; 1.0529x over previous
#include <cuda_runtime.h>
#include <stdint.h>

#define BB 4
#define NP 8192
#define NG 8192
#define T  256        // threads per block
#define Q  8          // queries per thread
#define SLA 16        // gt slices (acc direction)
#define PS 32         // pred slices (com direction)
#define PSL (NP / PS) // 256 pred points per slice
#define GRID_X (NP / (T * Q))          // 4
#define NZ (SLA * BB + PS * BB)        // 192
#define NBLK (GRID_X * NZ)             // 768 blocks, one tile each
#define NINIT 148                      // setup blocks (wave-1 co-resident)
#define TILE_MAX 512                   // max points per tile (8 KB smem)

#define INF_BITS 0x7F800000u

// ---------------- device scratch (no allocs; all state self-resets per replay) ----------------
__device__ float    g_gt[BB][3][NG];   // compacted valid gt, SoA ([cnt,NG) = stale, never used)
__device__ float    g_gtsq[BB][NG];    // |g|^2 per compacted gt
__device__ int      g_gtidx[BB][NG];   // original gt index of compacted entry
__device__ int      g_cnt[BB];         // zero-init (.bss); reset by last block each replay
__device__ unsigned g_prmin[BB * NP];  // per-pred min d2 (float bits)
__device__ unsigned g_gtmin[BB * NG];  // per-ORIGINAL-gt min d2 (float bits)
__device__ int      g_barA;            // setup-arrival counter
__device__ int      g_go;              // setup-complete release flag
__device__ int      g_done;            // completion counter

// ---------------- packed f32x2 helpers ----------------
__device__ __forceinline__ unsigned long long f2pk(float lo, float hi) {
    unsigned long long r;
    asm("mov.b64 %0, {%1,%2};" : "=l"(r) : "f"(lo), "f"(hi));
    return r;
}
__device__ __forceinline__ unsigned long long fma2(unsigned long long a, unsigned long long b,
                                                   unsigned long long c) {
    unsigned long long r;
    asm("fma.rn.f32x2 %0, %1, %2, %3;" : "=l"(r) : "l"(a), "l"(b), "l"(c));
    return r;
}
__device__ __forceinline__ void upk(unsigned long long v, float& lo, float& hi) {
    asm("mov.b64 {%0,%1}, %2;" : "=f"(lo), "=f"(hi) : "l"(v));
}

// ---------------- the single kernel: setup prologue + one static cd tile per block ----------------
__global__ void __launch_bounds__(T) k_all(const float* __restrict__ pr,
                                           const float* __restrict__ gt,
                                           const void* __restrict__ valid,
                                           float* __restrict__ out) {
    int tid = threadIdx.x;
    int bid = blockIdx.y * GRID_X + blockIdx.x;   // linear block id (x-major = launch order)

    // ======== Setup prologue: first NINIT blocks (wave-1 co-resident, bid-ordered) ========
    if (bid < NINIT) {
        int gtid = bid * T + tid;
        int gstride = NINIT * T;   // 37888 threads

        // reset min arrays
        for (int k = gtid; k < BB * NP; k += gstride) g_prmin[k] = INF_BITS;
        for (int k = gtid; k < BB * NG; k += gstride) g_gtmin[k] = INF_BITS;

        // BLOCK-LOCAL format detect: every setup block scans all 8192 words itself
        // (byte-bool packs 4 flags/word -> some word > 1; int32 words are all 0/1;
        //  reading (BB*NG)/4 words is safe under both layouts).
        __shared__ int s_bad;
        if (tid == 0) s_bad = 0;
        __syncthreads();
        {
            const unsigned* w = (const unsigned*)valid;
            int found = 0;
            for (int k = tid; k < (BB * NG) / 4; k += T)
                if (w[k] > 1u) found = 1;
            if (found) s_bad = 1;   // race-benign
        }
        __syncthreads();
        int fmt_byte = s_bad;

        // warp-aggregated compaction (first BB*NG global threads)
        if (gtid < BB * NG) {
            int b = gtid >> 13;     // / NG
            int g = gtid & (NG - 1);
            bool v;
            if (fmt_byte)
                v = (reinterpret_cast<const unsigned char*>(valid)[gtid] != 0);
            else
                v = (reinterpret_cast<const int*>(valid)[gtid] != 0);

            unsigned mask = __ballot_sync(0xffffffffu, v);
            int lane = tid & 31;
            int base = 0;
            if (lane == 0 && mask) base = atomicAdd(&g_cnt[b], __popc(mask));
            base = __shfl_sync(0xffffffffu, base, 0);
            if (v) {
                int p = base + __popc(mask & ((1u << lane) - 1u));
                const float* sgt = gt + (size_t)gtid * 3;
                float x = sgt[0], y = sgt[1], z = sgt[2];
                g_gt[b][0][p] = x;
                g_gt[b][1][p] = y;
                g_gt[b][2][p] = z;
                g_gtsq[b][p]  = x * x + y * y + z * z;
                g_gtidx[b][p] = g;
            }
        }

        // release: last setup block to arrive sets g_go
        __syncthreads();
        if (tid == 0) {
            __threadfence();
            int prev = atomicAdd(&g_barA, 1);
            if (prev == NINIT - 1) {
                __threadfence();
                *(volatile int*)&g_go = 1;
            }
        }
    }

    // ======== All blocks: wait for setup completion (plain-load spin, no atomic convoy) ========
    if (tid == 0) {
        while (*(volatile int*)&g_go == 0) __nanosleep(128);
        __threadfence();   // acquire setup writes
    }
    __syncthreads();

    // ======== One static cd tile (R6-verbatim body) ========
    // blockIdx.y = zz in [0,192): zz < 64 -> acc (b = zz>>4, slice = zz&15)
    //                             zz >= 64 -> com (b = (zz-64)>>5, slice = (zz-64)&31)
    {
        int zz = blockIdx.y;
        bool is_acc = zz < SLA * BB;
        int b, slice;
        if (is_acc) { b = zz >> 4; slice = zz & (SLA - 1); }
        else { int zc = zz - SLA * BB; b = zc >> 5; slice = zc & (PS - 1); }
        int cnt = g_cnt[b];

        __shared__ __align__(16) float4 s[TILE_MAX];  // 8 KB

        int qbase = blockIdx.x * (T * Q);
        bool active;
        int tileLen = 0, t0 = 0;
        if (is_acc) {
            int npad = (cnt + 7) & ~7;
            int L = (((npad + SLA - 1) / SLA) + 7) & ~7;   // slice len, mult of 8, <= 512
            t0 = slice * L;
            int t1 = min(t0 + L, npad);
            active = (t0 < t1);
            tileLen = active ? (t1 - t0) : 0;
        } else {
            t0 = slice * PSL;
            tileLen = PSL;
            active = (qbase < cnt);
        }

        if (active) {
            if (is_acc) {
                for (int i = tid; i < tileLen; i += T) {
                    int idx = t0 + i;
                    float x, y, z, sq;
                    if (idx < cnt) {
                        x = g_gt[b][0][idx]; y = g_gt[b][1][idx]; z = g_gt[b][2][idx];
                        sq = g_gtsq[b][idx];
                    } else {  // in-register sentinel (pad region, <= 7 entries)
                        x = 0.f; y = 0.f; z = 0.f; sq = __uint_as_float(INF_BITS);
                    }
                    float* base = reinterpret_cast<float*>(&s[(i >> 1) * 2]);
                    int h = i & 1;
                    base[0 + h] = x; base[2 + h] = y; base[4 + h] = z; base[6 + h] = sq;
                }
            } else {
                for (int i = tid; i < tileLen; i += T) {
                    const float* p = pr + ((size_t)b * NP + t0 + i) * 3;
                    float x = p[0], y = p[1], z = p[2];
                    float sq = x * x + y * y + z * z;
                    float* base = reinterpret_cast<float*>(&s[(i >> 1) * 2]);
                    int h = i & 1;
                    base[0 + h] = x; base[2 + h] = y; base[4 + h] = z; base[6 + h] = sq;
                }
            }
            __syncthreads();

            unsigned long long q2x[Q], q2y[Q], q2z[Q];
            float qsq[Q], m0[Q], m1[Q];
#pragma unroll
            for (int q = 0; q < Q; q++) {
                int qq = qbase + tid + q * T;
                float x, y, z, sq;
                if (is_acc) {
                    const float* p = pr + ((size_t)b * NP + qq) * 3;
                    x = p[0]; y = p[1]; z = p[2];
                    sq = x * x + y * y + z * z;
                } else {
                    // qq >= cnt reads stale data; result discarded at the atomic
                    x = g_gt[b][0][qq]; y = g_gt[b][1][qq]; z = g_gt[b][2][qq];
                    sq = (qq < cnt) ? g_gtsq[b][qq] : 0.f;
                }
                float nx = -2.f * x, ny = -2.f * y, nz = -2.f * z;
                q2x[q] = f2pk(nx, nx); q2y[q] = f2pk(ny, ny); q2z[q] = f2pk(nz, nz);
                qsq[q] = sq;
                m0[q] = __uint_as_float(INF_BITS);
                m1[q] = __uint_as_float(INF_BITS);
            }

            int pairs = tileLen >> 1;
#pragma unroll 2
            for (int k = 0; k < pairs; k++) {
                float4 a  = s[k * 2];
                float4 bv = s[k * 2 + 1];
                unsigned long long gx = f2pk(a.x, a.y);
                unsigned long long gy = f2pk(a.z, a.w);
                unsigned long long gz = f2pk(bv.x, bv.y);
                unsigned long long gs = f2pk(bv.z, bv.w);
#pragma unroll
                for (int q = 0; q < Q; q++) {
                    unsigned long long t = fma2(q2x[q], gx, fma2(q2y[q], gy, fma2(q2z[q], gz, gs)));
                    float tl, th; upk(t, tl, th);
                    m0[q] = fminf(m0[q], tl);
                    m1[q] = fminf(m1[q], th);
                }
            }

#pragma unroll
            for (int q = 0; q < Q; q++) {
                int qq = qbase + tid + q * T;
                float m = fmaxf(fminf(m0[q], m1[q]) + qsq[q], 0.f);
                if (is_acc) {
                    atomicMin(&g_prmin[b * NP + qq], __float_as_uint(m));
                } else if (qq < cnt) {
                    int orig = g_gtidx[b][qq];
                    atomicMin(&g_gtmin[b * NG + orig], __float_as_uint(m));
                }
            }
        }
    }

    // ======== Final: last block reduces + resets all state ========
    __shared__ bool isLast;
    __shared__ float sa;
    __shared__ float sc[BB];
    __threadfence();
    __syncthreads();
    if (tid == 0) {
        int prev = atomicAdd(&g_done, 1);
        isLast = (prev == NBLK - 1);
        if (isLast) __threadfence();   // acquire all blocks' writes
        sa = 0.f;
    }
    if (tid < BB) sc[tid] = 0.f;
    __syncthreads();
    if (!isLast) return;

    float la = 0.f;
    for (int i = tid; i < BB * NP; i += T)
        la += __uint_as_float(g_prmin[i]);
    atomicAdd(&sa, la);

    for (int bb = 0; bb < BB; bb++) {
        float lc = 0.f;
        for (int i = tid; i < NG; i += T) {
            unsigned v = g_gtmin[bb * NG + i];
            if (v != INF_BITS) lc += __uint_as_float(v);  // only valid gt were written
        }
        atomicAdd(&sc[bb], lc);
    }
    __syncthreads();

    if (tid == 0) {
        float loss_acc = sa / (float)(BB * NP);
        float loss_com = 0.f;
        for (int bb = 0; bb < BB; bb++)
            loss_com += sc[bb] / fmaxf((float)g_cnt[bb], 1.f);
        loss_com /= (float)BB;
        out[0] = 2.f * (loss_acc + loss_com);  // acc + com + cd, cd = acc + com

        // reset ALL mutable state for the next graph replay
        for (int bb = 0; bb < BB; bb++) g_cnt[bb] = 0;
        g_barA = 0;
        g_go = 0;
        g_done = 0;
    }
}

// ---------------- launch ----------------
extern "C" void kernel_launch(void* const* d_in, const int* in_sizes, int n_in,
                              void* d_out, int out_size) {
    const float* pr    = (const float*)d_in[0];  // [B,NP,3] f32
    const float* gt    = (const float*)d_in[1];  // [B,NG,3] f32
    const void*  valid = d_in[2];                // [B,NG] bool(1B) or int32

    k_all<<<dim3(GRID_X, NZ), T>>>(pr, gt, valid, (float*)d_out);
}